// round 14
// baseline (speedup 1.0000x reference)
#include <cuda_runtime.h>
#include <math.h>

// EGNN layer collapsed to the diagonal (eye-mask kills off-diagonal edges).
// Per row r:
//   t1 = silu(h@(We1a+We1b) + sqrt(EPS)*We1[2F] + be1)
//   t2 = silu(t1@We2 + be2)
//   att = sigmoid(t2.Wa + ba)                 [warp-uniform scalar]
//   t3 = silu(bn1 + h@Wn1a + att*(t2@Wn1b))   [att factored out]
//   out = t3@Wn2 + bn2
// FINAL FORM (R10 + balanced fill): uniform 147 blocks (1/SM) x 7 warps,
// 2 rows/warp; transposed smem weights (s[j*PAD+f], PAD=36) read as
// conflict-free lane-column LDS.128; att butterfly overlapped with S_t2.
// The fill distributes all 1280 float4 transpose jobs evenly (no straggler
// thread doing a 2nd full iteration before the barrier).

#define SQRT_EPS 0.0031622776601683794f  // sqrt(1e-5)
#define FULL 0xffffffffu
#define PAD 36
#define WARPS_PER_BLOCK 7
#define NTHREADS (32 * WARPS_PER_BLOCK)
#define ROWS_PER_BLOCK (WARPS_PER_BLOCK * 2)

__device__ __forceinline__ float silu_f(float v) {
    return __fdividef(v, 1.0f + __expf(-v));
}
__device__ __forceinline__ float sigmoid_f(float v) {
    return __fdividef(1.0f, 1.0f + __expf(-v));
}

__global__ void __launch_bounds__(NTHREADS, 1)
egnn_diag_kernel(const float* __restrict__ h,
                 const float* __restrict__ x,
                 const float* __restrict__ We1, const float* __restrict__ be1,
                 const float* __restrict__ We2, const float* __restrict__ be2,
                 const float* __restrict__ Wa,  const float* __restrict__ ba,
                 const float* __restrict__ Wn1, const float* __restrict__ bn1,
                 const float* __restrict__ Wn2, const float* __restrict__ bn2,
                 float* __restrict__ out, float* __restrict__ xout, int R)
{
    // transposed: s[j*PAD + f] = W[f][j]; lane j reads its column via LDS.128
    // Order matters for the flat fill indexing below.
    __shared__ __align__(16) float s_w1 [32 * PAD];  // We1a+We1b folded
    __shared__ __align__(16) float s_wna[32 * PAD];  // Wn1[0:F]
    __shared__ __align__(16) float s_wnb[32 * PAD];  // Wn1[F:2F]
    __shared__ __align__(16) float s_we2[32 * PAD];
    __shared__ __align__(16) float s_wn2[32 * PAD];

    const int tid  = threadIdx.x;
    const int lane = tid & 31;
    const int r0   = blockIdx.x * ROWS_PER_BLOCK + (tid >> 5) * 2;
    const int r1   = r0 + 1;

    // ---- balanced flat transposing fill: 5*256 = 1280 float4 jobs ----
    // job j: matrix m = j >> 8, slot i = j & 255.
    {
        float* const bases[5] = {s_w1, s_wna, s_wnb, s_we2, s_wn2};
        #pragma unroll
        for (int j = tid; j < 1280; j += NTHREADS) {
            const int m  = j >> 8;
            const int i  = j & 255;
            const int f  = i >> 3;            // 0..31 (row of W)
            const int j0 = (i & 7) * 4;       // col group
            float4 v;
            if (m == 0) {
                const float4 a = ((const float4*)We1)[i];
                const float4 b = ((const float4*)We1)[256 + i];
                v = make_float4(a.x + b.x, a.y + b.y, a.z + b.z, a.w + b.w);
            } else if (m == 1) {
                v = ((const float4*)Wn1)[i];
            } else if (m == 2) {
                v = ((const float4*)Wn1)[256 + i];
            } else if (m == 3) {
                v = ((const float4*)We2)[i];
            } else {
                v = ((const float4*)Wn2)[i];
            }
            float* s = bases[m];
            s[(j0 + 0) * PAD + f] = v.x;
            s[(j0 + 1) * PAD + f] = v.y;
            s[(j0 + 2) * PAD + f] = v.z;
            s[(j0 + 3) * PAD + f] = v.w;
        }
    }

    // ---- independent per-warp front work (overlaps fill latency) ----
    const bool has0 = (r0 < R);
    const bool has1 = (r1 < R);
    const float hv0 = has0 ? h[r0 * 32 + lane] : 0.f;
    const float hv1 = has1 ? h[r1 * 32 + lane] : 0.f;

    if (lane < 6 && r0 * 3 + lane < R * 3)       // x rows r0,r1 (6 floats)
        xout[r0 * 3 + lane] = x[r0 * 3 + lane];

    const float b1  = be1[lane] + SQRT_EPS * We1[64 * 32 + lane];
    const float b2  = be2[lane];
    const float wa  = Wa[lane];
    const float ba0 = ba[0];
    const float b3  = bn1[lane];
    const float b4  = bn2[lane];

    __syncthreads();
    if (!has0) return;

    const int col = lane * PAD;

    // ---- layer 1 + S_h fused (one weight vec feeds both rows) ----
    float a00 = b1, a10 = 0.f, a01 = b1, a11 = 0.f;
    float p00 = 0.f, p10 = 0.f, p01 = 0.f, p11 = 0.f;
    #pragma unroll
    for (int q = 0; q < 8; ++q) {
        const float4 w1 = *(const float4*)&s_w1 [col + 4 * q];
        const float4 wn = *(const float4*)&s_wna[col + 4 * q];
        const float h00 = __shfl_sync(FULL, hv0, 4 * q + 0);
        const float h01 = __shfl_sync(FULL, hv0, 4 * q + 1);
        const float h02 = __shfl_sync(FULL, hv0, 4 * q + 2);
        const float h03 = __shfl_sync(FULL, hv0, 4 * q + 3);
        const float h10 = __shfl_sync(FULL, hv1, 4 * q + 0);
        const float h11 = __shfl_sync(FULL, hv1, 4 * q + 1);
        const float h12 = __shfl_sync(FULL, hv1, 4 * q + 2);
        const float h13 = __shfl_sync(FULL, hv1, 4 * q + 3);
        a00 += h00 * w1.x;  a10 += h01 * w1.y;  a00 += h02 * w1.z;  a10 += h03 * w1.w;
        a01 += h10 * w1.x;  a11 += h11 * w1.y;  a01 += h12 * w1.z;  a11 += h13 * w1.w;
        p00 += h00 * wn.x;  p10 += h01 * wn.y;  p00 += h02 * wn.z;  p10 += h03 * wn.w;
        p01 += h10 * wn.x;  p11 += h11 * wn.y;  p01 += h12 * wn.z;  p11 += h13 * wn.w;
    }
    const float t1_0 = silu_f(a00 + a10);
    const float t1_1 = silu_f(a01 + a11);
    const float sh0 = p00 + p10;
    const float sh1 = p01 + p11;

    // ---- layer 2 ----
    a00 = b2; a10 = 0.f; a01 = b2; a11 = 0.f;
    #pragma unroll
    for (int q = 0; q < 8; ++q) {
        const float4 w2 = *(const float4*)&s_we2[col + 4 * q];
        a00 += __shfl_sync(FULL, t1_0, 4 * q + 0) * w2.x;
        a10 += __shfl_sync(FULL, t1_0, 4 * q + 1) * w2.y;
        a00 += __shfl_sync(FULL, t1_0, 4 * q + 2) * w2.z;
        a10 += __shfl_sync(FULL, t1_0, 4 * q + 3) * w2.w;
        a01 += __shfl_sync(FULL, t1_1, 4 * q + 0) * w2.x;
        a11 += __shfl_sync(FULL, t1_1, 4 * q + 1) * w2.y;
        a01 += __shfl_sync(FULL, t1_1, 4 * q + 2) * w2.z;
        a11 += __shfl_sync(FULL, t1_1, 4 * q + 3) * w2.w;
    }
    const float t2_0 = silu_f(a00 + a10);
    const float t2_1 = silu_f(a01 + a11);

    // ---- att butterfly overlapped with S_t2 = t2 @ Wn1b ----
    float s0 = t2_0 * wa;
    float s1 = t2_1 * wa;
    p00 = 0.f; p10 = 0.f; p01 = 0.f; p11 = 0.f;
    #pragma unroll
    for (int q = 0; q < 8; ++q) {
        const float4 wb = *(const float4*)&s_wnb[col + 4 * q];
        p00 += __shfl_sync(FULL, t2_0, 4 * q + 0) * wb.x;
        p10 += __shfl_sync(FULL, t2_0, 4 * q + 1) * wb.y;
        p00 += __shfl_sync(FULL, t2_0, 4 * q + 2) * wb.z;
        p10 += __shfl_sync(FULL, t2_0, 4 * q + 3) * wb.w;
        p01 += __shfl_sync(FULL, t2_1, 4 * q + 0) * wb.x;
        p11 += __shfl_sync(FULL, t2_1, 4 * q + 1) * wb.y;
        p01 += __shfl_sync(FULL, t2_1, 4 * q + 2) * wb.z;
        p11 += __shfl_sync(FULL, t2_1, 4 * q + 3) * wb.w;
    }
    #pragma unroll
    for (int off = 16; off > 0; off >>= 1) {
        s0 += __shfl_xor_sync(FULL, s0, off);
        s1 += __shfl_xor_sync(FULL, s1, off);
    }
    const float att0 = sigmoid_f(s0 + ba0);
    const float att1 = sigmoid_f(s1 + ba0);

    // ---- layer 3 epilogue ----
    const float t3_0 = silu_f(b3 + sh0 + att0 * (p00 + p10));
    const float t3_1 = silu_f(b3 + sh1 + att1 * (p01 + p11));

    // ---- layer 4 ----
    a00 = b4; a10 = 0.f; a01 = b4; a11 = 0.f;
    #pragma unroll
    for (int q = 0; q < 8; ++q) {
        const float4 w4 = *(const float4*)&s_wn2[col + 4 * q];
        a00 += __shfl_sync(FULL, t3_0, 4 * q + 0) * w4.x;
        a10 += __shfl_sync(FULL, t3_0, 4 * q + 1) * w4.y;
        a00 += __shfl_sync(FULL, t3_0, 4 * q + 2) * w4.z;
        a10 += __shfl_sync(FULL, t3_0, 4 * q + 3) * w4.w;
        a01 += __shfl_sync(FULL, t3_1, 4 * q + 0) * w4.x;
        a11 += __shfl_sync(FULL, t3_1, 4 * q + 1) * w4.y;
        a01 += __shfl_sync(FULL, t3_1, 4 * q + 2) * w4.z;
        a11 += __shfl_sync(FULL, t3_1, 4 * q + 3) * w4.w;
    }

    out[r0 * 32 + lane] = a00 + a10;
    if (has1) out[r1 * 32 + lane] = a01 + a11;
}

extern "C" void kernel_launch(void* const* d_in, const int* in_sizes, int n_in,
                              void* d_out, int out_size)
{
    const float* h   = (const float*)d_in[0];
    const float* x   = (const float*)d_in[1];
    const float* We1 = (const float*)d_in[2];
    const float* be1 = (const float*)d_in[3];
    const float* We2 = (const float*)d_in[4];
    const float* be2 = (const float*)d_in[5];
    const float* Wa  = (const float*)d_in[6];
    const float* ba  = (const float*)d_in[7];
    const float* Wn1 = (const float*)d_in[8];
    const float* bn1 = (const float*)d_in[9];
    const float* Wn2 = (const float*)d_in[10];
    const float* bn2 = (const float*)d_in[11];

    const int R = in_sizes[0] / 32;          // B*N rows
    float* out  = (float*)d_out;             // [R, 32]
    float* xout = out + (size_t)R * 32;      // [R, 3] passthrough

    const int blocks = (R + ROWS_PER_BLOCK - 1) / ROWS_PER_BLOCK;  // 147
    egnn_diag_kernel<<<blocks, NTHREADS>>>(h, x, We1, be1, We2, be2, Wa, ba,
                                           Wn1, bn1, Wn2, bn2, out, xout, R);
}

// round 15
// speedup vs baseline: 1.0373x; 1.0373x over previous
#include <cuda_runtime.h>
#include <math.h>

// EGNN layer collapsed to the diagonal (eye-mask kills off-diagonal edges).
// Per row r:
//   t1 = silu(h@(We1a+We1b) + sqrt(EPS)*We1[2F] + be1)
//   t2 = silu(t1@We2 + be2)
//   att = sigmoid(t2.Wa + ba)                 [warp-uniform scalar]
//   t3 = silu(bn1 + h@Wn1a + att*(t2@Wn1b))   [att factored out]
//   out = t3@Wn2 + bn2
// FINAL (R10, session best: ncu 6.98us / bench 8.64us): uniform 147 blocks
// (1 per SM) x 7 warps, 2 rows/warp; transposed smem weights (s[j*PAD+f],
// PAD=36) read as conflict-free lane-column LDS.128; straight-line
// cooperative fill; att butterfly overlapped with the S_t2 accumulation.

#define SQRT_EPS 0.0031622776601683794f  // sqrt(1e-5)
#define FULL 0xffffffffu
#define PAD 36
#define WARPS_PER_BLOCK 7
#define ROWS_PER_BLOCK (WARPS_PER_BLOCK * 2)

__device__ __forceinline__ float silu_f(float v) {
    return __fdividef(v, 1.0f + __expf(-v));
}
__device__ __forceinline__ float sigmoid_f(float v) {
    return __fdividef(1.0f, 1.0f + __expf(-v));
}

__global__ void __launch_bounds__(32 * WARPS_PER_BLOCK, 1)
egnn_diag_kernel(const float* __restrict__ h,
                 const float* __restrict__ x,
                 const float* __restrict__ We1, const float* __restrict__ be1,
                 const float* __restrict__ We2, const float* __restrict__ be2,
                 const float* __restrict__ Wa,  const float* __restrict__ ba,
                 const float* __restrict__ Wn1, const float* __restrict__ bn1,
                 const float* __restrict__ Wn2, const float* __restrict__ bn2,
                 float* __restrict__ out, float* __restrict__ xout, int R)
{
    // transposed: s[j*PAD + f] = W[f][j]; lane j reads its column via LDS.128
    __shared__ __align__(16) float s_w1 [32 * PAD];  // We1a+We1b folded
    __shared__ __align__(16) float s_wna[32 * PAD];  // Wn1[0:F]
    __shared__ __align__(16) float s_wnb[32 * PAD];  // Wn1[F:2F]
    __shared__ __align__(16) float s_we2[32 * PAD];
    __shared__ __align__(16) float s_wn2[32 * PAD];

    const int tid  = threadIdx.x;
    const int lane = tid & 31;
    const int r0   = blockIdx.x * ROWS_PER_BLOCK + (tid >> 5) * 2;
    const int r1   = r0 + 1;

    // ---- cooperative transposing fill: 256 float4 slots, 224 threads ----
    for (int i = tid; i < 256; i += 32 * WARPS_PER_BLOCK) {
        const int f  = i >> 3;            // 0..31 (row of W)
        const int j0 = (i & 7) * 4;       // col group
        const float4 a  = ((const float4*)We1)[i];
        const float4 b  = ((const float4*)We1)[256 + i];
        s_w1[(j0 + 0) * PAD + f] = a.x + b.x;
        s_w1[(j0 + 1) * PAD + f] = a.y + b.y;
        s_w1[(j0 + 2) * PAD + f] = a.z + b.z;
        s_w1[(j0 + 3) * PAD + f] = a.w + b.w;
        const float4 na = ((const float4*)Wn1)[i];
        s_wna[(j0 + 0) * PAD + f] = na.x;
        s_wna[(j0 + 1) * PAD + f] = na.y;
        s_wna[(j0 + 2) * PAD + f] = na.z;
        s_wna[(j0 + 3) * PAD + f] = na.w;
        const float4 nb = ((const float4*)Wn1)[256 + i];
        s_wnb[(j0 + 0) * PAD + f] = nb.x;
        s_wnb[(j0 + 1) * PAD + f] = nb.y;
        s_wnb[(j0 + 2) * PAD + f] = nb.z;
        s_wnb[(j0 + 3) * PAD + f] = nb.w;
        const float4 e2 = ((const float4*)We2)[i];
        s_we2[(j0 + 0) * PAD + f] = e2.x;
        s_we2[(j0 + 1) * PAD + f] = e2.y;
        s_we2[(j0 + 2) * PAD + f] = e2.z;
        s_we2[(j0 + 3) * PAD + f] = e2.w;
        const float4 n2 = ((const float4*)Wn2)[i];
        s_wn2[(j0 + 0) * PAD + f] = n2.x;
        s_wn2[(j0 + 1) * PAD + f] = n2.y;
        s_wn2[(j0 + 2) * PAD + f] = n2.z;
        s_wn2[(j0 + 3) * PAD + f] = n2.w;
    }

    // ---- independent per-warp front work (overlaps fill latency) ----
    const bool has0 = (r0 < R);
    const bool has1 = (r1 < R);
    const float hv0 = has0 ? h[r0 * 32 + lane] : 0.f;
    const float hv1 = has1 ? h[r1 * 32 + lane] : 0.f;

    if (lane < 6 && r0 * 3 + lane < R * 3)       // x rows r0,r1 (6 floats)
        xout[r0 * 3 + lane] = x[r0 * 3 + lane];

    const float b1  = be1[lane] + SQRT_EPS * We1[64 * 32 + lane];
    const float b2  = be2[lane];
    const float wa  = Wa[lane];
    const float ba0 = ba[0];
    const float b3  = bn1[lane];
    const float b4  = bn2[lane];

    __syncthreads();
    if (!has0) return;

    const int col = lane * PAD;

    // ---- layer 1 + S_h fused (one weight vec feeds both rows) ----
    float a00 = b1, a10 = 0.f, a01 = b1, a11 = 0.f;
    float p00 = 0.f, p10 = 0.f, p01 = 0.f, p11 = 0.f;
    #pragma unroll
    for (int q = 0; q < 8; ++q) {
        const float4 w1 = *(const float4*)&s_w1 [col + 4 * q];
        const float4 wn = *(const float4*)&s_wna[col + 4 * q];
        const float h00 = __shfl_sync(FULL, hv0, 4 * q + 0);
        const float h01 = __shfl_sync(FULL, hv0, 4 * q + 1);
        const float h02 = __shfl_sync(FULL, hv0, 4 * q + 2);
        const float h03 = __shfl_sync(FULL, hv0, 4 * q + 3);
        const float h10 = __shfl_sync(FULL, hv1, 4 * q + 0);
        const float h11 = __shfl_sync(FULL, hv1, 4 * q + 1);
        const float h12 = __shfl_sync(FULL, hv1, 4 * q + 2);
        const float h13 = __shfl_sync(FULL, hv1, 4 * q + 3);
        a00 += h00 * w1.x;  a10 += h01 * w1.y;  a00 += h02 * w1.z;  a10 += h03 * w1.w;
        a01 += h10 * w1.x;  a11 += h11 * w1.y;  a01 += h12 * w1.z;  a11 += h13 * w1.w;
        p00 += h00 * wn.x;  p10 += h01 * wn.y;  p00 += h02 * wn.z;  p10 += h03 * wn.w;
        p01 += h10 * wn.x;  p11 += h11 * wn.y;  p01 += h12 * wn.z;  p11 += h13 * wn.w;
    }
    const float t1_0 = silu_f(a00 + a10);
    const float t1_1 = silu_f(a01 + a11);
    const float sh0 = p00 + p10;
    const float sh1 = p01 + p11;

    // ---- layer 2 ----
    a00 = b2; a10 = 0.f; a01 = b2; a11 = 0.f;
    #pragma unroll
    for (int q = 0; q < 8; ++q) {
        const float4 w2 = *(const float4*)&s_we2[col + 4 * q];
        a00 += __shfl_sync(FULL, t1_0, 4 * q + 0) * w2.x;
        a10 += __shfl_sync(FULL, t1_0, 4 * q + 1) * w2.y;
        a00 += __shfl_sync(FULL, t1_0, 4 * q + 2) * w2.z;
        a10 += __shfl_sync(FULL, t1_0, 4 * q + 3) * w2.w;
        a01 += __shfl_sync(FULL, t1_1, 4 * q + 0) * w2.x;
        a11 += __shfl_sync(FULL, t1_1, 4 * q + 1) * w2.y;
        a01 += __shfl_sync(FULL, t1_1, 4 * q + 2) * w2.z;
        a11 += __shfl_sync(FULL, t1_1, 4 * q + 3) * w2.w;
    }
    const float t2_0 = silu_f(a00 + a10);
    const float t2_1 = silu_f(a01 + a11);

    // ---- att butterfly overlapped with S_t2 = t2 @ Wn1b ----
    float s0 = t2_0 * wa;
    float s1 = t2_1 * wa;
    p00 = 0.f; p10 = 0.f; p01 = 0.f; p11 = 0.f;
    #pragma unroll
    for (int q = 0; q < 8; ++q) {
        const float4 wb = *(const float4*)&s_wnb[col + 4 * q];
        p00 += __shfl_sync(FULL, t2_0, 4 * q + 0) * wb.x;
        p10 += __shfl_sync(FULL, t2_0, 4 * q + 1) * wb.y;
        p00 += __shfl_sync(FULL, t2_0, 4 * q + 2) * wb.z;
        p10 += __shfl_sync(FULL, t2_0, 4 * q + 3) * wb.w;
        p01 += __shfl_sync(FULL, t2_1, 4 * q + 0) * wb.x;
        p11 += __shfl_sync(FULL, t2_1, 4 * q + 1) * wb.y;
        p01 += __shfl_sync(FULL, t2_1, 4 * q + 2) * wb.z;
        p11 += __shfl_sync(FULL, t2_1, 4 * q + 3) * wb.w;
    }
    #pragma unroll
    for (int off = 16; off > 0; off >>= 1) {
        s0 += __shfl_xor_sync(FULL, s0, off);
        s1 += __shfl_xor_sync(FULL, s1, off);
    }
    const float att0 = sigmoid_f(s0 + ba0);
    const float att1 = sigmoid_f(s1 + ba0);

    // ---- layer 3 epilogue ----
    const float t3_0 = silu_f(b3 + sh0 + att0 * (p00 + p10));
    const float t3_1 = silu_f(b3 + sh1 + att1 * (p01 + p11));

    // ---- layer 4 ----
    a00 = b4; a10 = 0.f; a01 = b4; a11 = 0.f;
    #pragma unroll
    for (int q = 0; q < 8; ++q) {
        const float4 w4 = *(const float4*)&s_wn2[col + 4 * q];
        a00 += __shfl_sync(FULL, t3_0, 4 * q + 0) * w4.x;
        a10 += __shfl_sync(FULL, t3_0, 4 * q + 1) * w4.y;
        a00 += __shfl_sync(FULL, t3_0, 4 * q + 2) * w4.z;
        a10 += __shfl_sync(FULL, t3_0, 4 * q + 3) * w4.w;
        a01 += __shfl_sync(FULL, t3_1, 4 * q + 0) * w4.x;
        a11 += __shfl_sync(FULL, t3_1, 4 * q + 1) * w4.y;
        a01 += __shfl_sync(FULL, t3_1, 4 * q + 2) * w4.z;
        a11 += __shfl_sync(FULL, t3_1, 4 * q + 3) * w4.w;
    }

    out[r0 * 32 + lane] = a00 + a10;
    if (has1) out[r1 * 32 + lane] = a01 + a11;
}

extern "C" void kernel_launch(void* const* d_in, const int* in_sizes, int n_in,
                              void* d_out, int out_size)
{
    const float* h   = (const float*)d_in[0];
    const float* x   = (const float*)d_in[1];
    const float* We1 = (const float*)d_in[2];
    const float* be1 = (const float*)d_in[3];
    const float* We2 = (const float*)d_in[4];
    const float* be2 = (const float*)d_in[5];
    const float* Wa  = (const float*)d_in[6];
    const float* ba  = (const float*)d_in[7];
    const float* Wn1 = (const float*)d_in[8];
    const float* bn1 = (const float*)d_in[9];
    const float* Wn2 = (const float*)d_in[10];
    const float* bn2 = (const float*)d_in[11];

    const int R = in_sizes[0] / 32;          // B*N rows
    float* out  = (float*)d_out;             // [R, 32]
    float* xout = out + (size_t)R * 32;      // [R, 3] passthrough

    const int threads = 32 * WARPS_PER_BLOCK;                       // 224
    const int blocks  = (R + ROWS_PER_BLOCK - 1) / ROWS_PER_BLOCK;  // 147
    egnn_diag_kernel<<<blocks, threads>>>(h, x, We1, be1, We2, be2, Wa, ba,
                                          Wn1, bn1, Wn2, bn2, out, xout, R);
}